// round 7
// baseline (speedup 1.0000x reference)
#include <cuda_runtime.h>

// Soft-DTW, gamma = 0.01, p = 2, B = 64, M = N = 512.
// One CTA per batch. 256 threads, thread jj owns columns (2jj, 2jj+1).
// Anti-diagonal wavefront, NO per-step __syncthreads:
//   - intra-warp left-neighbor exchange via __shfl_up_sync
//   - cross-warp boundary via shared buffer + release/acquire progress counters
// At step s thread jj computes A = (s-2jj, 2jj) and B = (s-2jj-1, 2jj+1).
//   A deps: up = own A(s-1), left = nb B(s-1) [shfl], diag = nb B(s-2) [prev shfl]
//   B deps: up = own B(s-1), left = own A(s-1), diag = own A(s-2)   [all registers]

#define BIG   1e30f
#define KEXP  144.26950408889634f    // 100 * log2(e)
#define GLN2  0.006931471805599453f  // 0.01 * ln(2)

__device__ __forceinline__ float ex2f_(float v) {
    float r; asm("ex2.approx.ftz.f32 %0, %1;" : "=f"(r) : "f"(v)); return r;
}
__device__ __forceinline__ float lg2f_(float v) {
    float r; asm("lg2.approx.ftz.f32 %0, %1;" : "=f"(r) : "f"(v)); return r;
}
__device__ __forceinline__ int ld_acq(const int* p) {
    int v; asm volatile("ld.acquire.cta.s32 %0, [%1];" : "=r"(v) : "l"(p) : "memory"); return v;
}
__device__ __forceinline__ void st_rel(int* p, int v) {
    asm volatile("st.release.cta.s32 [%0], %1;" :: "l"(p), "r"(v) : "memory");
}

// softmin3 = m - gamma*ln(1 + e^{(m-v1)/g} + e^{(m-v2)/g}), m = min of three
__device__ __forceinline__ float softmin3(float dg, float up, float lf) {
    float t1 = fminf(dg, up);
    float t2 = fmaxf(dg, up);
    float m  = fminf(t1, lf);
    float u  = fmaxf(t1, lf);
    float mk = m * KEXP;
    float a1 = fmaf(-KEXP, t2, mk);   // <= 0
    float a2 = fmaf(-KEXP, u,  mk);   // <= 0
    float ss = 1.0f + ex2f_(a1) + ex2f_(a2);
    return fmaf(-GLN2, lg2f_(ss), m);
}

__global__ __launch_bounds__(256, 1)
void softdtw_kernel(const float* __restrict__ x,
                    const float* __restrict__ y,
                    float* __restrict__ out)
{
    __shared__ float ysh[512];
    __shared__ float bnd[7][1024];   // bnd[w][s]: warp w's lane-31 B value at step s
    __shared__ int   cnt[8];         // cnt[w] = highest step published by warp w

    const int b    = blockIdx.x;
    const int jj   = threadIdx.x;          // 0..255
    const int w    = jj >> 5;              // warp 0..7
    const int lane = jj & 31;
    const int colA = 2 * jj;
    const int colB = colA + 1;

    // init
    ysh[colA] = y[b * 512 + colA];
    ysh[colB] = y[b * 512 + colB];
    if (jj < 8) cnt[jj] = -1;
    const float xA = x[b * 512 + colA];
    const float xB = x[b * 512 + colB];
    __syncthreads();   // the ONLY full barrier

    const int sBeg     = 64 * w;
    const int sEnd     = min(1022, 64 * w + 574);
    const int sPollMax = 64 * w + 511;     // last step whose boundary value matters

    float aPrev  = BIG;                    // A(s-1)
    float aPrev2 = BIG;                    // A(s-2)
    float bPrev  = BIG;                    // B(s-1)
    float nbPrev = (jj == 0) ? 0.0f : BIG; // neighbor B(s-2); R[-1,-1]=0 seed

    // y register rotation: yA = y[iA], yB = y[iA-1]
    int   iA0 = sBeg - colA;
    float yA  = ysh[min(max(iA0, 0), 511)];
    float yB  = ysh[min(max(iA0 - 1, 0), 511)];

    int cntCache = -1;

    #pragma unroll 2
    for (int s = sBeg; s <= sEnd; ++s) {
        const int iA = s - colA;           // row of A; row of B = iA-1

        // cross-warp boundary value for lane 0 (neighbor warp's lane-31 B at s-1)
        float bndv = BIG;
        if (w > 0 && s <= sPollMax) {
            if (cntCache < s - 1) {
                do { cntCache = ld_acq(&cnt[w - 1]); } while (cntCache < s - 1);
            }
            bndv = bnd[w - 1][s - 1];
        }

        float nbCur = __shfl_up_sync(0xffffffffu, bPrev, 1);
        if (lane == 0) nbCur = bndv;

        // B cell (register-only deps) — compute first to hide shfl/LDS latency
        float tB = xB - yB;
        float rB = softmin3(aPrev2, bPrev, aPrev) + tB * tB;
        rB = ((unsigned)(iA - 1) < 512u) ? rB : BIG;

        // A cell
        float tA = xA - yA;
        float rA = softmin3(nbPrev, aPrev, nbCur) + tA * tA;
        rA = ((unsigned)iA < 512u) ? rA : BIG;

        // publish boundary (lane 31 of warps 0..6)
        if (lane == 31 && w < 7) {
            bnd[w][s] = rB;
            st_rel(&cnt[w], s);
        }

        // rotate state
        aPrev2 = aPrev;
        aPrev  = rA;
        bPrev  = rB;
        nbPrev = nbCur;
        yB = yA;
        yA = ysh[min(max(iA + 1, 0), 511)];
    }

    if (jj == 255) out[b] = bPrev;   // B at s=1022 -> R[511,511]
}

extern "C" void kernel_launch(void* const* d_in, const int* in_sizes, int n_in,
                              void* d_out, int out_size)
{
    const float* x = (const float*)d_in[0];
    const float* y = (const float*)d_in[1];
    float* out = (float*)d_out;
    softdtw_kernel<<<64, 256>>>(x, y, out);
}